// round 8
// baseline (speedup 1.0000x reference)
#include <cuda_runtime.h>

// Problem constants
#define NN 512
#define KK 17
#define WW 48
#define HH 64
#define NK (NN * KK)                       // 8704
#define HMSZ (HH * WW)                     // 3072
#define TOTAL ((double)NN * KK * HH * WW)  // 26738688

// Per-heatmap separable gaussian tables (static device scratch, ~3.9 MB)
__device__ __align__(16) float g_ex[NK * WW];   // [NK][48]
__device__ float g_ey[NK * HH];                 // [NK][64]
__device__ float g_coef[NK];                    // [NK]

__device__ double g_acc;          // zero-initialized; reset by last block each run
__device__ unsigned int g_cnt;    // ditto

// ---------------- Kernel 1: build tables (trivial) ----------------
__global__ __launch_bounds__(128) void table_kernel(
    const float* __restrict__ pred,      // [N,K,2]
    const float* __restrict__ sigma,     // [N,K,2]
    const float* __restrict__ twgt)      // [N,K,1]
{
    const int nk  = blockIdx.x;
    const int tid = threadIdx.x;

    // Uniform loads (same address per warp -> broadcast)
    const float mux = pred[nk * 2 + 0] * (float)WW;
    const float muy = pred[nk * 2 + 1] * (float)HH;
    const float sx  = sigma[nk * 2 + 0];
    const float sy  = sigma[nk * 2 + 1];

    if (tid < WW) {
        float invx = 1.0f / (sx * sx + 1e-9f);
        float d = (float)tid - mux;
        g_ex[nk * WW + tid] = __expf(-0.5f * d * d * invx);
    } else if (tid == WW) {
        float m = ((mux - 3.0f * sx < (float)WW) &&
                   (muy - 3.0f * sy < (float)HH) &&
                   (mux + 3.0f * sx + 1.0f >= 0.0f) &&
                   (muy + 3.0f * sy + 1.0f >= 0.0f)) ? 1.0f : 0.0f;
        float tw = twgt[nk] * m;
        g_coef[nk] = tw * tw;
    } else if (tid >= 64) {
        float invy = 1.0f / (sy * sy + 1e-9f);
        int h = tid - 64;
        float d = (float)h - muy;
        g_ey[nk * HH + h] = __expf(-0.5f * d * d * invy);
    }
}

// ---------------- Kernel 2: barrier-free streaming reduce ----------------
__global__ __launch_bounds__(256) void reg2hm_loss_kernel(
    const float* __restrict__ teacher,   // [N,K,H,W]
    float* __restrict__ out)             // [1]
{
    const int nk  = blockIdx.x;          // 0..NK-1
    const int tid = threadIdx.x;

    // Thread-fixed quad coords (12 float4 per row, W=48)
    const int q0 = tid,        h0 = q0 / 12, c0 = q0 % 12;
    const int q1 = tid + 256,  h1 = q1 / 12, c1 = q1 % 12;
    const int q2 = tid + 512,  h2 = q2 / 12, c2 = q2 % 12;

    // ---- Front-batch ALL loads (no barrier, no dependency above them) ----
    const float4* __restrict__ tp  = reinterpret_cast<const float4*>(teacher + (size_t)nk * HMSZ);
    const float4* __restrict__ ex4 = reinterpret_cast<const float4*>(g_ex + nk * WW);
    const float*  __restrict__ eyr = g_ey + nk * HH;

    const float4 t0 = tp[q0];
    const float4 t1 = tp[q1];
    const float4 t2 = tp[q2];
    const float4 e0 = ex4[c0];           // L1-resident after first warp touches row
    const float4 e1 = ex4[c1];
    const float4 e2 = ex4[c2];
    const float  y0 = eyr[h0];
    const float  y1 = eyr[h1];
    const float  y2 = eyr[h2];
    const float  coef = g_coef[nk];

    // ---- 24 FFMA ----
    float d0 = e0.x * y0 - t0.x;
    float d1 = e0.y * y0 - t0.y;
    float d2 = e0.z * y0 - t0.z;
    float d3 = e0.w * y0 - t0.w;
    float s  = d0 * d0 + d1 * d1 + d2 * d2 + d3 * d3;
    d0 = e1.x * y1 - t1.x;
    d1 = e1.y * y1 - t1.y;
    d2 = e1.z * y1 - t1.z;
    d3 = e1.w * y1 - t1.w;
    s += d0 * d0 + d1 * d1 + d2 * d2 + d3 * d3;
    d0 = e2.x * y2 - t2.x;
    d1 = e2.y * y2 - t2.y;
    d2 = e2.z * y2 - t2.z;
    d3 = e2.w * y2 - t2.w;
    s += d0 * d0 + d1 * d1 + d2 * d2 + d3 * d3;
    s *= coef;

    // ---- Block reduce (single barrier in the whole kernel) ----
    __shared__ float s_warp[8];
#pragma unroll
    for (int off = 16; off > 0; off >>= 1)
        s += __shfl_down_sync(0xFFFFFFFFu, s, off);
    if ((tid & 31) == 0) s_warp[tid >> 5] = s;
    __syncthreads();

    if (tid < 8) {
        float v = s_warp[tid];
#pragma unroll
        for (int off = 4; off > 0; off >>= 1)
            v += __shfl_down_sync(0x000000FFu, v, off);
        if (tid == 0) {
            atomicAdd(&g_acc, (double)v);
            __threadfence();
            unsigned int ticket = atomicAdd(&g_cnt, 1u);
            if (ticket == NK - 1) {
                double total = atomicAdd(&g_acc, 0.0);   // coherent read
                out[0] = (float)(total / TOTAL);         // LOSS_WEIGHT = 1.0
                g_acc = 0.0;                             // reset for next replay
                g_cnt = 0u;
            }
        }
    }
}

extern "C" void kernel_launch(void* const* d_in, const int* in_sizes, int n_in,
                              void* d_out, int out_size) {
    const float* pred    = (const float*)d_in[0];
    const float* sigma   = (const float*)d_in[1];
    const float* teacher = (const float*)d_in[2];
    const float* twgt    = (const float*)d_in[3];
    float* out = (float*)d_out;

    table_kernel<<<NK, 128>>>(pred, sigma, twgt);
    reg2hm_loss_kernel<<<NK, 256>>>(teacher, out);
}